// round 10
// baseline (speedup 1.0000x reference)
#include <cuda_runtime.h>

#define NM 8192
#define NB 2
#define V0 642
#define V1 2562
#define V2 10242
#define E0 1920
#define E1 7680
#define E2 30720
#define CHAM_UNITS 3648
#define LAP_BLOCKS 108
#define TOTAL_BLOCKS (CHAM_UNITS + LAP_BLOCKS)
#define EPI_BLOCKS 615
#define INF_F __int_as_float(0x7f800000)

// ---------------- scratch (device globals; zero-init == armed for atomicMax) ----------------
__device__ unsigned long long g_keyA[NB * (V0 + V1 + V2)]; // (~ford(d') << 32) | (~m)
__device__ unsigned int       g_minB[3 * NB * NM];         // ~ford(d')
__device__ double             g_acc[18]; // 0-2 predsum 3-5 gtsum 6-8 edge 9-11 normal 12-14 lap 15-17 move
__device__ unsigned int       g_done;

// ---------------- helpers ----------------
static __device__ __forceinline__ unsigned long long pack2(float lo, float hi) {
    unsigned long long r;
    asm("mov.b64 %0,{%1,%2};" : "=l"(r) : "f"(lo), "f"(hi));
    return r;
}
static __device__ __forceinline__ void unpack2(unsigned long long v, float& lo, float& hi) {
    asm("mov.b64 {%0,%1},%2;" : "=f"(lo), "=f"(hi) : "l"(v));
}
static __device__ __forceinline__ unsigned long long fma2(unsigned long long a,
                                                          unsigned long long b,
                                                          unsigned long long c) {
    unsigned long long d;
    asm("fma.rn.f32x2 %0,%1,%2,%3;" : "=l"(d) : "l"(a), "l"(b), "l"(c));
    return d;
}
// monotone float->uint (handles negatives); stored inverted so 0 == "+inf armed"
static __device__ __forceinline__ unsigned int ford(float f) {
    unsigned int b = __float_as_uint(f);
    return b ^ (0x80000000u | (unsigned int)(((int)b) >> 31));
}
static __device__ __forceinline__ float funord(unsigned int u) {
    unsigned int b = (u & 0x80000000u) ? (u ^ 0x80000000u) : ~u;
    return __uint_as_float(b);
}

// block-level f64 accumulate: 2 atomics per block instead of per warp
static __device__ __forceinline__ void block_acc(int t, float val, float val2,
                                                 int slot, int slot2)
{
    __shared__ float s1[8], s2[8];
#pragma unroll
    for (int o = 16; o; o >>= 1) {
        val  += __shfl_down_sync(0xffffffffu, val, o);
        val2 += __shfl_down_sync(0xffffffffu, val2, o);
    }
    if ((t & 31) == 0) { s1[t >> 5] = val; s2[t >> 5] = val2; }
    __syncthreads();
    if (t == 0) {
        float a = 0.f, b = 0.f;
#pragma unroll
        for (int w = 0; w < 8; w++) { a += s1[w]; b += s2[w]; }
        atomicAdd(&g_acc[slot], (double)a);
        if (slot2 >= 0) atomicAdd(&g_acc[slot2], (double)b);
    }
}

// ---------------- chamfer inner loop: 64 packed steps over a 128-pt tile ----------------
template <bool ARGMIN>
static __device__ __forceinline__ void inner_loop(
    const ulonglong2* __restrict__ sXY, const ulonglong2* __restrict__ sZW,
    const unsigned long long* ax2, const unsigned long long* ay2, const unsigned long long* az2,
    float* bd, int* bm, int mbase)
{
#pragma unroll 4
    for (int j = 0; j < 64; j++) {
        ulonglong2 xy = sXY[j];
        ulonglong2 zw = sZW[j];
#pragma unroll
        for (int k = 0; k < 4; k++) {
            unsigned long long d = fma2(az2[k], zw.x, zw.y);
            d = fma2(ay2[k], xy.y, d);
            d = fma2(ax2[k], xy.x, d);
            float lo, hi;
            unpack2(d, lo, hi);
            if (ARGMIN) {
                // select-form: FMNMX + SEL (pred-as-data), index chain off the min chain
                bool c0 = lo < bd[k];
                bm[k] = c0 ? (mbase + 2 * j) : bm[k];
                bd[k] = fminf(lo, bd[k]);
                bool c1 = hi < bd[k];
                bm[k] = c1 ? (mbase + 2 * j + 1) : bm[k];
                bd[k] = fminf(hi, bd[k]);
            } else {
                bd[k] = fminf(bd[k], lo);
                bd[k] = fminf(bd[k], hi);
            }
        }
    }
}

// ---------------- chamfer + lap/move (plain grid; 128-pt tiles; lap blocks LAST) ----------
// unit map (id = bk): A2 [0,1408) B2 [1408,2704) A1 [2704,3088) B1 [3088,3424)
//                     A0 [3424,3552) B0 [3552,3648); lap [3648,3756)
__global__ __launch_bounds__(256, 4) void chamfer_kernel(
    const float* __restrict__ p0l, const float* __restrict__ p1l, const float* __restrict__ p2l,
    const float* __restrict__ b0l, const float* __restrict__ b1l, const float* __restrict__ b2l,
    const int* __restrict__ l0l, const int* __restrict__ l1l, const int* __restrict__ l2l,
    const float* __restrict__ gt)
{
    __shared__ ulonglong2 sXY[64], sZW[64];
    const int bk = blockIdx.x;
    const int t = threadIdx.x;

    if (bk >= CHAM_UNITS) {
        // ---- laplace + move (short blocks; placed last to backfill the final wave) ----
        const int lk = bk - CHAM_UNITS;
        int lvl, base; const float *pred, *bef; const int* lap; int V;
        if (lk < 6)       { lvl = 0; base = lk * 256;        pred = p0l; bef = b0l; lap = l0l; V = V0; }
        else if (lk < 27) { lvl = 1; base = (lk - 6) * 256;  pred = p1l; bef = b1l; lap = l1l; V = V1; }
        else              { lvl = 2; base = (lk - 27) * 256; pred = p2l; bef = b2l; lap = l2l; V = V2; }
        int idx = base + t;
        float val = 0.f, val2 = 0.f;
        if (idx < NB * V) {
            int bb = idx / V, v = idx - bb * V;
            const int* row = lap + (size_t)v * 10;
            float cnt = (float)row[9];
            float sx = 0.f, sy = 0.f, sz = 0.f;
#pragma unroll
            for (int j = 0; j < 8; j++) {
                int nid = row[j];
                if (nid >= 0) {
                    const float* pb = bef + ((size_t)bb * V + nid) * 3;
                    const float* pp = pred + ((size_t)bb * V + nid) * 3;
                    sx += pb[0] - pp[0];
                    sy += pb[1] - pp[1];
                    sz += pb[2] - pp[2];
                }
            }
            const float* bv = bef + ((size_t)bb * V + v) * 3;
            const float* pv = pred + ((size_t)bb * V + v) * 3;
            float dx = bv[0] - pv[0], dy = bv[1] - pv[1], dz = bv[2] - pv[2];
            float lx = dx - sx / cnt, ly = dy - sy / cnt, lz = dz - sz / cnt;
            val = lx * lx + ly * ly + lz * lz;
            val2 = dx * dx + dy * dy + dz * dz;
        }
        block_acc(t, val, val2, 12 + lvl, (lvl > 0) ? 15 + lvl : -1);
        return;
    }

    int lvl, isA, u;
    if (bk < 1408)      { lvl = 2; isA = 1; u = bk; }
    else if (bk < 2704) { lvl = 2; isA = 0; u = bk - 1408; }
    else if (bk < 3088) { lvl = 1; isA = 1; u = bk - 2704; }
    else if (bk < 3424) { lvl = 1; isA = 0; u = bk - 3088; }
    else if (bk < 3552) { lvl = 0; isA = 1; u = bk - 3424; }
    else                { lvl = 0; isA = 0; u = bk - 3552; }
    const int b = u & 1; u >>= 1;
    int chunk, slice;
    if (isA) { slice = u & 63; chunk = u >> 6; }   // 64 gt-slices of 128
    else     { chunk = u & 7;  slice = u >> 3; }   // 8 gt-chunks of 1024; pred vtiles of 128

    const float* pred = (lvl == 0) ? p0l : (lvl == 1 ? p1l : p2l);
    const int V = (lvl == 0) ? V0 : (lvl == 1 ? V1 : V2);

    unsigned long long ax2[4], ay2[4], az2[4];
    float bd[4] = {INF_F, INF_F, INF_F, INF_F};
    int bm[4] = {0, 0, 0, 0};

    if (isA) {
        // points = pred, loop dim = gt tile of 128 (always full)
        const int mtile = slice * 128;
        if (t < 64) {
            const float2* gp = (const float2*)(gt + ((size_t)b * NM + mtile) * 3);
            float2 f0 = gp[3 * t], f1 = gp[3 * t + 1], f2 = gp[3 * t + 2];
            float x0 = f0.x, y0 = f0.y, z0 = f1.x, x1 = f1.y, y1 = f2.x, z1 = f2.y;
            sXY[t] = make_ulonglong2(pack2(x0, x1), pack2(y0, y1));
            sZW[t] = make_ulonglong2(pack2(z0, z1),
                                     pack2(x0 * x0 + y0 * y0 + z0 * z0,
                                           x1 * x1 + y1 * y1 + z1 * z1));
        }
        const int vb = chunk * 1024 + t;
#pragma unroll
        for (int k = 0; k < 4; k++) {
            float px = 0.f, py = 0.f, pz = 0.f;
            int v = vb + 256 * k;
            if (v < V) {
                const float* pp = pred + ((size_t)b * V + v) * 3;
                px = pp[0]; py = pp[1]; pz = pp[2];
            }
            ax2[k] = pack2(-2.f * px, -2.f * px);
            ay2[k] = pack2(-2.f * py, -2.f * py);
            az2[k] = pack2(-2.f * pz, -2.f * pz);
        }
        __syncthreads();
        if (vb < V) {
            if (b == 0) inner_loop<true >(sXY, sZW, ax2, ay2, az2, bd, bm, mtile);
            else        inner_loop<false>(sXY, sZW, ax2, ay2, az2, bd, bm, mtile);
            const int keyOff = (lvl >= 1 ? NB * V0 : 0) + (lvl >= 2 ? NB * V1 : 0);
#pragma unroll
            for (int k = 0; k < 4; k++) {
                int v = vb + 256 * k;
                if (v < V) {
                    unsigned long long key =
                        ((unsigned long long)(~ford(bd[k])) << 32) | (unsigned int)(~bm[k]);
                    atomicMax(&g_keyA[keyOff + b * V + v], key);
                }
            }
        }
    } else {
        // points = gt (always valid), loop dim = pred tile of 128 (pad tail with +inf)
        const int vtile = slice * 128;
        const int n = (V - vtile < 128) ? (V - vtile) : 128;
        if (t < 64) {
            float x0 = 0.f, y0 = 0.f, z0 = 0.f, w0 = INF_F;
            float x1 = 0.f, y1 = 0.f, z1 = 0.f, w1 = INF_F;
            int i0 = 2 * t, i1 = 2 * t + 1;
            if (i0 < n) {
                const float* pp = pred + ((size_t)b * V + vtile + i0) * 3;
                x0 = pp[0]; y0 = pp[1]; z0 = pp[2];
                w0 = x0 * x0 + y0 * y0 + z0 * z0;
            }
            if (i1 < n) {
                const float* pp = pred + ((size_t)b * V + vtile + i1) * 3;
                x1 = pp[0]; y1 = pp[1]; z1 = pp[2];
                w1 = x1 * x1 + y1 * y1 + z1 * z1;
            }
            sXY[t] = make_ulonglong2(pack2(x0, x1), pack2(y0, y1));
            sZW[t] = make_ulonglong2(pack2(z0, z1), pack2(w0, w1));
        }
        const int mb = chunk * 1024 + t;
#pragma unroll
        for (int k = 0; k < 4; k++) {
            const float* gp = gt + ((size_t)b * NM + mb + 256 * k) * 3;
            float gx = gp[0], gy = gp[1], gz = gp[2];
            ax2[k] = pack2(-2.f * gx, -2.f * gx);
            ay2[k] = pack2(-2.f * gy, -2.f * gy);
            az2[k] = pack2(-2.f * gz, -2.f * gz);
        }
        __syncthreads();
        inner_loop<false>(sXY, sZW, ax2, ay2, az2, bd, bm, 0);
        const int minOff = lvl * NB * NM;
#pragma unroll
        for (int k = 0; k < 4; k++)
            atomicMax(&g_minB[minOff + b * NM + mb + 256 * k], ~ford(bd[k]));
    }
}

// ---------------- epilogue: edge+normal / finA / finB / combine ----------
__global__ __launch_bounds__(256) void epi_kernel(
    const float* __restrict__ p0l, const float* __restrict__ p1l, const float* __restrict__ p2l,
    const int* __restrict__ e0l, const int* __restrict__ e1l, const int* __restrict__ e2l,
    const float* __restrict__ gt, const float* __restrict__ gtn,
    float* __restrict__ out)
{
    const int bk = blockIdx.x, t = threadIdx.x;
    float val = 0.f, val2 = 0.f;
    int slot = -1, slot2 = -1;

    if (bk < 315) {
        int lvl, base; const float* pred; const int* edges; int V, E, keyOff;
        if (bk < 15)      { lvl = 0; base = bk * 256;        pred = p0l; edges = e0l; V = V0; E = E0; keyOff = 0; }
        else if (bk < 75) { lvl = 1; base = (bk - 15) * 256; pred = p1l; edges = e1l; V = V1; E = E1; keyOff = NB * V0; }
        else              { lvl = 2; base = (bk - 75) * 256; pred = p2l; edges = e2l; V = V2; E = E2; keyOff = NB * (V0 + V1); }
        int idx = base + t;
        if (idx < NB * E) {
            int bb = idx / E, e = idx - bb * E;
            int e0 = edges[2 * e], e1 = edges[2 * e + 1];
            const float* a = pred + ((size_t)bb * V + e0) * 3;
            const float* c = pred + ((size_t)bb * V + e1) * 3;
            float dx = a[0] - c[0], dy = a[1] - c[1], dz = a[2] - c[2];
            float sq = dx * dx + dy * dy + dz * dz;
            val = sq;
            float inv = 1.f / fmaxf(sqrtf(sq), 1e-12f);
            unsigned int sel = ~(unsigned int)(g_keyA[keyOff + e0] & 0xFFFFFFFFull); // b=0 knn
            const float* g = gtn + ((size_t)bb * NM + sel) * 3;
            float gx = g[0], gy = g[1], gz = g[2];
            float gi = 1.f / fmaxf(sqrtf(gx * gx + gy * gy + gz * gz), 1e-12f);
            val2 = fabsf((dx * gx + dy * gy + dz * gz) * inv * gi);
        }
        slot = 6 + lvl;
        slot2 = 9 + lvl;
    } else if (bk < 423) {
        int lvl, base; const float* pred; int V, keyOff;
        if (bk < 321)      { lvl = 0; base = (bk - 315) * 256; pred = p0l; V = V0; keyOff = 0; }
        else if (bk < 342) { lvl = 1; base = (bk - 321) * 256; pred = p1l; V = V1; keyOff = NB * V0; }
        else               { lvl = 2; base = (bk - 342) * 256; pred = p2l; V = V2; keyOff = NB * (V0 + V1); }
        int idx = base + t;
        if (idx < NB * V) {
            unsigned long long key = g_keyA[keyOff + idx];
            int bb = idx / V, v = idx - bb * V;
            const float* pp = pred + ((size_t)bb * V + v) * 3;
            float p2 = pp[0] * pp[0] + pp[1] * pp[1] + pp[2] * pp[2];
            val = funord(~(unsigned int)(key >> 32)) + p2;
        }
        slot = lvl;
    } else {
        int lvl = (bk - 423) >> 6;
        int idx = ((bk - 423) & 63) * 256 + t;
        unsigned int u = g_minB[lvl * NB * NM + idx];
        int bb = idx >> 13, m = idx & (NM - 1);
        const float* gp = gt + ((size_t)bb * NM + m) * 3;
        val = funord(~u) + gp[0] * gp[0] + gp[1] * gp[1] + gp[2] * gp[2];
        slot = 3 + lvl;
    }

    block_acc(t, val, val2, slot, slot2);

    __threadfence();
    __syncthreads();
    if (t == 0) {
        unsigned int ticket = atomicAdd(&g_done, 1u);
        if (ticket == EPI_BLOCKS - 1) {
            double a[18];
#pragma unroll
            for (int i = 0; i < 18; i++) a[i] = __ldcg(&g_acc[i]);
            const double Vd[3] = {642.0, 2562.0, 10242.0};
            const double Ed[3] = {1920.0, 7680.0, 30720.0};
            const double LAPC[3] = {0.2, 1.0, 1.0};
            double chamfer = 0, edge = 0, nrm = 0, lap = 0, move = 0;
            for (int i = 0; i < 3; i++) {
                chamfer += a[3 + i] / (2.0 * 8192.0) + a[i] / (2.0 * Vd[i]);
                edge += a[6 + i] / (2.0 * Ed[i]);
                nrm += a[9 + i] / (2.0 * Ed[i]);
                lap += LAPC[i] * a[12 + i] / (2.0 * Vd[i]);
                if (i > 0) move += LAPC[i] * a[15 + i] / (2.0 * Vd[i]);
            }
            out[0] = (float)(chamfer + 0.5 * lap + 0.1 * move + 0.1 * edge + 0.00016 * nrm);
#pragma unroll
            for (int i = 0; i < 18; i++) g_acc[i] = 0.0;
            g_done = 0u;
        }
    }
}

// ---------------- profiling alignment nops (5 launches/call => ncu -s5 lands on chamfer) ----
__global__ void nop1_kernel() {}
__global__ void nop2_kernel() {}
__global__ void nop3_kernel() {}

// ---------------- launcher ----------------
extern "C" void kernel_launch(void* const* d_in, const int* in_sizes, int n_in,
                              void* d_out, int out_size)
{
    (void)out_size;
    const float *pred[3] = {0, 0, 0}, *before[3] = {0, 0, 0}, *gt = 0, *gtn = 0;
    const int *lap[3] = {0, 0, 0}, *edges[3] = {0, 0, 0};
    int c0 = 0, c1 = 0, c2 = 0, cg = 0;
    for (int i = 0; i < n_in; i++) {
        int s = in_sizes[i];
        const void* p = d_in[i];
        switch (s) {
            case 3852:  if (c0++ == 0) pred[0] = (const float*)p; else before[0] = (const float*)p; break;
            case 15372: if (c1++ == 0) pred[1] = (const float*)p; else before[1] = (const float*)p; break;
            case 61452: if (c2++ == 0) pred[2] = (const float*)p; else before[2] = (const float*)p; break;
            case 49152: if (cg++ == 0) gt = (const float*)p; else gtn = (const float*)p; break;
            case 6420:   lap[0] = (const int*)p; break;
            case 25620:  lap[1] = (const int*)p; break;
            case 102420: lap[2] = (const int*)p; break;
            case 3840:   edges[0] = (const int*)p; break;
            case 15360:  edges[1] = (const int*)p; break;
            case 61440:  edges[2] = (const int*)p; break;
            default: break;
        }
    }

    chamfer_kernel<<<TOTAL_BLOCKS, 256>>>(
        pred[0], pred[1], pred[2],
        before[0], before[1], before[2],
        lap[0], lap[1], lap[2], gt);
    epi_kernel<<<EPI_BLOCKS, 256>>>(pred[0], pred[1], pred[2],
                                    edges[0], edges[1], edges[2],
                                    gt, gtn, (float*)d_out);
    nop1_kernel<<<1, 32>>>();
    nop2_kernel<<<1, 32>>>();
    nop3_kernel<<<1, 32>>>();
}

// round 12
// speedup vs baseline: 1.0237x; 1.0237x over previous
#include <cuda_runtime.h>

#define NM 8192
#define NB 2
#define V0 642
#define V1 2562
#define V2 10242
#define E0 1920
#define E1 7680
#define E2 30720
#define CHAM_UNITS 3648
#define LAP_BLOCKS 108
#define TOTAL_BLOCKS (CHAM_UNITS + LAP_BLOCKS)
#define EPI_BLOCKS 615
#define INF_F __int_as_float(0x7f800000)

// ---------------- scratch (device globals; zero-init == armed for atomicMax) ----------------
__device__ unsigned long long g_keyA[NB * (V0 + V1 + V2)]; // (~ford(d') << 32) | (~m)
__device__ unsigned int       g_minB[3 * NB * NM];         // ~ford(d')
__device__ double             g_acc[18]; // 0-2 predsum 3-5 gtsum 6-8 edge 9-11 normal 12-14 lap 15-17 move
__device__ unsigned int       g_done;

// ---------------- helpers ----------------
static __device__ __forceinline__ unsigned long long pack2(float lo, float hi) {
    unsigned long long r;
    asm("mov.b64 %0,{%1,%2};" : "=l"(r) : "f"(lo), "f"(hi));
    return r;
}
static __device__ __forceinline__ void unpack2(unsigned long long v, float& lo, float& hi) {
    asm("mov.b64 {%0,%1},%2;" : "=f"(lo), "=f"(hi) : "l"(v));
}
static __device__ __forceinline__ unsigned long long fma2(unsigned long long a,
                                                          unsigned long long b,
                                                          unsigned long long c) {
    unsigned long long d;
    asm("fma.rn.f32x2 %0,%1,%2,%3;" : "=l"(d) : "l"(a), "l"(b), "l"(c));
    return d;
}
// monotone float->uint (handles negatives); stored inverted so 0 == "+inf armed"
static __device__ __forceinline__ unsigned int ford(float f) {
    unsigned int b = __float_as_uint(f);
    return b ^ (0x80000000u | (unsigned int)(((int)b) >> 31));
}
static __device__ __forceinline__ float funord(unsigned int u) {
    unsigned int b = (u & 0x80000000u) ? (u ^ 0x80000000u) : ~u;
    return __uint_as_float(b);
}

// block-level f64 accumulate: 2 atomics per block instead of per warp
static __device__ __forceinline__ void block_acc(int t, float val, float val2,
                                                 int slot, int slot2)
{
    __shared__ float s1[8], s2[8];
#pragma unroll
    for (int o = 16; o; o >>= 1) {
        val  += __shfl_down_sync(0xffffffffu, val, o);
        val2 += __shfl_down_sync(0xffffffffu, val2, o);
    }
    if ((t & 31) == 0) { s1[t >> 5] = val; s2[t >> 5] = val2; }
    __syncthreads();
    if (t == 0) {
        float a = 0.f, b = 0.f;
#pragma unroll
        for (int w = 0; w < 8; w++) { a += s1[w]; b += s2[w]; }
        atomicAdd(&g_acc[slot], (double)a);
        if (slot2 >= 0) atomicAdd(&g_acc[slot2], (double)b);
    }
}

// ---------------- min-only inner loop: 64 packed steps over a 128-pt tile ----------------
static __device__ __forceinline__ void inner_min(
    const ulonglong2* __restrict__ sXY, const ulonglong2* __restrict__ sZW,
    const unsigned long long* ax2, const unsigned long long* ay2, const unsigned long long* az2,
    float* bd)
{
#pragma unroll 4
    for (int j = 0; j < 64; j++) {
        ulonglong2 xy = sXY[j];
        ulonglong2 zw = sZW[j];
#pragma unroll
        for (int k = 0; k < 4; k++) {
            unsigned long long d = fma2(az2[k], zw.x, zw.y);
            d = fma2(ay2[k], xy.y, d);
            d = fma2(ax2[k], xy.x, d);
            float lo, hi;
            unpack2(d, lo, hi);
            bd[k] = fminf(bd[k], lo);
            bd[k] = fminf(bd[k], hi);
        }
    }
}

// ---------------- argmin inner loop: select-form, scalar accumulators ----------------
static __device__ __forceinline__ void inner_argmin(
    const ulonglong2* __restrict__ sXY, const ulonglong2* __restrict__ sZW,
    const unsigned long long* ax2, const unsigned long long* ay2, const unsigned long long* az2,
    float* bd, int* bm, int mbase)
{
#pragma unroll 4
    for (int j = 0; j < 64; j++) {
        ulonglong2 xy = sXY[j];
        ulonglong2 zw = sZW[j];
#pragma unroll
        for (int k = 0; k < 4; k++) {
            unsigned long long d = fma2(az2[k], zw.x, zw.y);
            d = fma2(ay2[k], xy.y, d);
            d = fma2(ax2[k], xy.x, d);
            float lo, hi;
            unpack2(d, lo, hi);
            bool c0 = lo < bd[k];
            bm[k] = c0 ? (mbase + 2 * j) : bm[k];
            bd[k] = fminf(lo, bd[k]);
            bool c1 = hi < bd[k];
            bm[k] = c1 ? (mbase + 2 * j + 1) : bm[k];
            bd[k] = fminf(hi, bd[k]);
        }
    }
}

// ---------------- chamfer + lap/move (plain grid; 128-pt tiles; lap blocks LAST) ----------
// unit map (id = bk): A2 [0,1408) B2 [1408,2704) A1 [2704,3088) B1 [3088,3424)
//                     A0 [3424,3552) B0 [3552,3648); lap [3648,3756)
__global__ __launch_bounds__(256, 4) void chamfer_kernel(
    const float* __restrict__ p0l, const float* __restrict__ p1l, const float* __restrict__ p2l,
    const float* __restrict__ b0l, const float* __restrict__ b1l, const float* __restrict__ b2l,
    const int* __restrict__ l0l, const int* __restrict__ l1l, const int* __restrict__ l2l,
    const float* __restrict__ gt)
{
    __shared__ ulonglong2 sXY[64], sZW[64];
    const int bk = blockIdx.x;
    const int t = threadIdx.x;

    if (bk >= CHAM_UNITS) {
        // ---- laplace + move (short blocks; placed last to backfill the final wave) ----
        const int lk = bk - CHAM_UNITS;
        int lvl, base; const float *pred, *bef; const int* lap; int V;
        if (lk < 6)       { lvl = 0; base = lk * 256;        pred = p0l; bef = b0l; lap = l0l; V = V0; }
        else if (lk < 27) { lvl = 1; base = (lk - 6) * 256;  pred = p1l; bef = b1l; lap = l1l; V = V1; }
        else              { lvl = 2; base = (lk - 27) * 256; pred = p2l; bef = b2l; lap = l2l; V = V2; }
        int idx = base + t;
        float val = 0.f, val2 = 0.f;
        if (idx < NB * V) {
            int bb = idx / V, v = idx - bb * V;
            const int* row = lap + (size_t)v * 10;
            float cnt = (float)row[9];
            float sx = 0.f, sy = 0.f, sz = 0.f;
#pragma unroll
            for (int j = 0; j < 8; j++) {
                int nid = row[j];
                if (nid >= 0) {
                    const float* pb = bef + ((size_t)bb * V + nid) * 3;
                    const float* pp = pred + ((size_t)bb * V + nid) * 3;
                    sx += pb[0] - pp[0];
                    sy += pb[1] - pp[1];
                    sz += pb[2] - pp[2];
                }
            }
            const float* bv = bef + ((size_t)bb * V + v) * 3;
            const float* pv = pred + ((size_t)bb * V + v) * 3;
            float dx = bv[0] - pv[0], dy = bv[1] - pv[1], dz = bv[2] - pv[2];
            float lx = dx - sx / cnt, ly = dy - sy / cnt, lz = dz - sz / cnt;
            val = lx * lx + ly * ly + lz * lz;
            val2 = dx * dx + dy * dy + dz * dz;
        }
        block_acc(t, val, val2, 12 + lvl, (lvl > 0) ? 15 + lvl : -1);
        cudaTriggerProgrammaticLaunchCompletion();
        return;
    }

    int lvl, isA, u;
    if (bk < 1408)      { lvl = 2; isA = 1; u = bk; }
    else if (bk < 2704) { lvl = 2; isA = 0; u = bk - 1408; }
    else if (bk < 3088) { lvl = 1; isA = 1; u = bk - 2704; }
    else if (bk < 3424) { lvl = 1; isA = 0; u = bk - 3088; }
    else if (bk < 3552) { lvl = 0; isA = 1; u = bk - 3424; }
    else                { lvl = 0; isA = 0; u = bk - 3552; }
    const int b = u & 1; u >>= 1;
    int chunk, slice;
    if (isA) { slice = u & 63; chunk = u >> 6; }   // 64 gt-slices of 128
    else     { chunk = u & 7;  slice = u >> 3; }   // 8 gt-chunks of 1024; pred vtiles of 128

    const float* pred = (lvl == 0) ? p0l : (lvl == 1 ? p1l : p2l);
    const int V = (lvl == 0) ? V0 : (lvl == 1 ? V1 : V2);

    unsigned long long ax2[4], ay2[4], az2[4];
    float bd[4] = {INF_F, INF_F, INF_F, INF_F};
    int bm[4] = {0, 0, 0, 0};

    if (isA) {
        // points = pred, loop dim = gt tile of 128 (always full)
        const int mtile = slice * 128;
        if (t < 64) {
            const float2* gp = (const float2*)(gt + ((size_t)b * NM + mtile) * 3);
            float2 f0 = gp[3 * t], f1 = gp[3 * t + 1], f2 = gp[3 * t + 2];
            float x0 = f0.x, y0 = f0.y, z0 = f1.x, x1 = f1.y, y1 = f2.x, z1 = f2.y;
            sXY[t] = make_ulonglong2(pack2(x0, x1), pack2(y0, y1));
            sZW[t] = make_ulonglong2(pack2(z0, z1),
                                     pack2(x0 * x0 + y0 * y0 + z0 * z0,
                                           x1 * x1 + y1 * y1 + z1 * z1));
        }
        const int vb = chunk * 1024 + t;
#pragma unroll
        for (int k = 0; k < 4; k++) {
            float px = 0.f, py = 0.f, pz = 0.f;
            int v = vb + 256 * k;
            if (v < V) {
                const float* pp = pred + ((size_t)b * V + v) * 3;
                px = pp[0]; py = pp[1]; pz = pp[2];
            }
            ax2[k] = pack2(-2.f * px, -2.f * px);
            ay2[k] = pack2(-2.f * py, -2.f * py);
            az2[k] = pack2(-2.f * pz, -2.f * pz);
        }
        __syncthreads();
        if (vb < V) {
            if (b == 0) inner_argmin(sXY, sZW, ax2, ay2, az2, bd, bm, mtile);
            else        inner_min(sXY, sZW, ax2, ay2, az2, bd);
            const int keyOff = (lvl >= 1 ? NB * V0 : 0) + (lvl >= 2 ? NB * V1 : 0);
#pragma unroll
            for (int k = 0; k < 4; k++) {
                int v = vb + 256 * k;
                if (v < V) {
                    unsigned long long key =
                        ((unsigned long long)(~ford(bd[k])) << 32) | (unsigned int)(~bm[k]);
                    atomicMax(&g_keyA[keyOff + b * V + v], key);
                }
            }
        }
    } else {
        // points = gt (always valid), loop dim = pred tile of 128 (pad tail with +inf)
        const int vtile = slice * 128;
        const int n = (V - vtile < 128) ? (V - vtile) : 128;
        if (t < 64) {
            float x0 = 0.f, y0 = 0.f, z0 = 0.f, w0 = INF_F;
            float x1 = 0.f, y1 = 0.f, z1 = 0.f, w1 = INF_F;
            int i0 = 2 * t, i1 = 2 * t + 1;
            if (i0 < n) {
                const float* pp = pred + ((size_t)b * V + vtile + i0) * 3;
                x0 = pp[0]; y0 = pp[1]; z0 = pp[2];
                w0 = x0 * x0 + y0 * y0 + z0 * z0;
            }
            if (i1 < n) {
                const float* pp = pred + ((size_t)b * V + vtile + i1) * 3;
                x1 = pp[0]; y1 = pp[1]; z1 = pp[2];
                w1 = x1 * x1 + y1 * y1 + z1 * z1;
            }
            sXY[t] = make_ulonglong2(pack2(x0, x1), pack2(y0, y1));
            sZW[t] = make_ulonglong2(pack2(z0, z1), pack2(w0, w1));
        }
        const int mb = chunk * 1024 + t;
#pragma unroll
        for (int k = 0; k < 4; k++) {
            const float* gp = gt + ((size_t)b * NM + mb + 256 * k) * 3;
            float gx = gp[0], gy = gp[1], gz = gp[2];
            ax2[k] = pack2(-2.f * gx, -2.f * gx);
            ay2[k] = pack2(-2.f * gy, -2.f * gy);
            az2[k] = pack2(-2.f * gz, -2.f * gz);
        }
        __syncthreads();
        inner_min(sXY, sZW, ax2, ay2, az2, bd);
        const int minOff = lvl * NB * NM;
#pragma unroll
        for (int k = 0; k < 4; k++)
            atomicMax(&g_minB[minOff + b * NM + mb + 256 * k], ~ford(bd[k]));
    }
    cudaTriggerProgrammaticLaunchCompletion();
}

// ---------------- epilogue (PDL): independent prologue, grid-sync, dependent reads --------
__global__ __launch_bounds__(256) void epi_kernel(
    const float* __restrict__ p0l, const float* __restrict__ p1l, const float* __restrict__ p2l,
    const int* __restrict__ e0l, const int* __restrict__ e1l, const int* __restrict__ e2l,
    const float* __restrict__ gt, const float* __restrict__ gtn,
    float* __restrict__ out)
{
    const int bk = blockIdx.x, t = threadIdx.x;
    float val = 0.f, val2 = 0.f;
    int slot = -1, slot2 = -1;

    if (bk < 315) {
        // ---- edge + normal ----
        int lvl, base; const float* pred; const int* edges; int V, E, keyOff;
        if (bk < 15)      { lvl = 0; base = bk * 256;        pred = p0l; edges = e0l; V = V0; E = E0; keyOff = 0; }
        else if (bk < 75) { lvl = 1; base = (bk - 15) * 256; pred = p1l; edges = e1l; V = V1; E = E1; keyOff = NB * V0; }
        else              { lvl = 2; base = (bk - 75) * 256; pred = p2l; edges = e2l; V = V2; E = E2; keyOff = NB * (V0 + V1); }
        int idx = base + t;
        // independent prologue
        int bb = 0, e0 = 0;
        float dx = 0.f, dy = 0.f, dz = 0.f, sq = 0.f, inv = 1.f;
        bool act = (idx < NB * E);
        if (act) {
            bb = idx / E;
            int e = idx - bb * E;
            e0 = edges[2 * e];
            int e1 = edges[2 * e + 1];
            const float* a = pred + ((size_t)bb * V + e0) * 3;
            const float* c = pred + ((size_t)bb * V + e1) * 3;
            dx = a[0] - c[0]; dy = a[1] - c[1]; dz = a[2] - c[2];
            sq = dx * dx + dy * dy + dz * dz;
            inv = 1.f / fmaxf(sqrtf(sq), 1e-12f);
        }
        cudaGridDependencySynchronize();
        if (act) {
            val = sq;
            unsigned int sel = ~(unsigned int)(g_keyA[keyOff + e0] & 0xFFFFFFFFull); // b=0 knn
            const float* g = gtn + ((size_t)bb * NM + sel) * 3;
            float gx = g[0], gy = g[1], gz = g[2];
            float gi = 1.f / fmaxf(sqrtf(gx * gx + gy * gy + gz * gz), 1e-12f);
            val2 = fabsf((dx * gx + dy * gy + dz * gz) * inv * gi);
        }
        slot = 6 + lvl;
        slot2 = 9 + lvl;
    } else if (bk < 423) {
        // ---- finA ----
        int lvl, base; const float* pred; int V, keyOff;
        if (bk < 321)      { lvl = 0; base = (bk - 315) * 256; pred = p0l; V = V0; keyOff = 0; }
        else if (bk < 342) { lvl = 1; base = (bk - 321) * 256; pred = p1l; V = V1; keyOff = NB * V0; }
        else               { lvl = 2; base = (bk - 342) * 256; pred = p2l; V = V2; keyOff = NB * (V0 + V1); }
        int idx = base + t;
        float p2 = 0.f;
        bool act = (idx < NB * V);
        if (act) {
            int bb = idx / V, v = idx - bb * V;
            const float* pp = pred + ((size_t)bb * V + v) * 3;
            p2 = pp[0] * pp[0] + pp[1] * pp[1] + pp[2] * pp[2];
        }
        cudaGridDependencySynchronize();
        if (act) {
            unsigned long long key = g_keyA[keyOff + idx];
            val = funord(~(unsigned int)(key >> 32)) + p2;
        }
        slot = lvl;
    } else {
        // ---- finB ----
        int lvl = (bk - 423) >> 6;
        int idx = ((bk - 423) & 63) * 256 + t;
        int bb = idx >> 13, m = idx & (NM - 1);
        const float* gp = gt + ((size_t)bb * NM + m) * 3;
        float g2 = gp[0] * gp[0] + gp[1] * gp[1] + gp[2] * gp[2];
        cudaGridDependencySynchronize();
        unsigned int u = g_minB[lvl * NB * NM + idx];
        val = funord(~u) + g2;
        slot = 3 + lvl;
    }

    block_acc(t, val, val2, slot, slot2);

    __threadfence();
    __syncthreads();
    if (t == 0) {
        unsigned int ticket = atomicAdd(&g_done, 1u);
        if (ticket == EPI_BLOCKS - 1) {
            double a[18];
#pragma unroll
            for (int i = 0; i < 18; i++) a[i] = __ldcg(&g_acc[i]);
            const double Vd[3] = {642.0, 2562.0, 10242.0};
            const double Ed[3] = {1920.0, 7680.0, 30720.0};
            const double LAPC[3] = {0.2, 1.0, 1.0};
            double chamfer = 0, edge = 0, nrm = 0, lap = 0, move = 0;
            for (int i = 0; i < 3; i++) {
                chamfer += a[3 + i] / (2.0 * 8192.0) + a[i] / (2.0 * Vd[i]);
                edge += a[6 + i] / (2.0 * Ed[i]);
                nrm += a[9 + i] / (2.0 * Ed[i]);
                lap += LAPC[i] * a[12 + i] / (2.0 * Vd[i]);
                if (i > 0) move += LAPC[i] * a[15 + i] / (2.0 * Vd[i]);
            }
            out[0] = (float)(chamfer + 0.5 * lap + 0.1 * move + 0.1 * edge + 0.00016 * nrm);
#pragma unroll
            for (int i = 0; i < 18; i++) g_acc[i] = 0.0;
            g_done = 0u;
        }
    }
}

// ---------------- launcher ----------------
extern "C" void kernel_launch(void* const* d_in, const int* in_sizes, int n_in,
                              void* d_out, int out_size)
{
    (void)out_size;
    const float *pred[3] = {0, 0, 0}, *before[3] = {0, 0, 0}, *gt = 0, *gtn = 0;
    const int *lap[3] = {0, 0, 0}, *edges[3] = {0, 0, 0};
    int c0 = 0, c1 = 0, c2 = 0, cg = 0;
    for (int i = 0; i < n_in; i++) {
        int s = in_sizes[i];
        const void* p = d_in[i];
        switch (s) {
            case 3852:  if (c0++ == 0) pred[0] = (const float*)p; else before[0] = (const float*)p; break;
            case 15372: if (c1++ == 0) pred[1] = (const float*)p; else before[1] = (const float*)p; break;
            case 61452: if (c2++ == 0) pred[2] = (const float*)p; else before[2] = (const float*)p; break;
            case 49152: if (cg++ == 0) gt = (const float*)p; else gtn = (const float*)p; break;
            case 6420:   lap[0] = (const int*)p; break;
            case 25620:  lap[1] = (const int*)p; break;
            case 102420: lap[2] = (const int*)p; break;
            case 3840:   edges[0] = (const int*)p; break;
            case 15360:  edges[1] = (const int*)p; break;
            case 61440:  edges[2] = (const int*)p; break;
            default: break;
        }
    }

    chamfer_kernel<<<TOTAL_BLOCKS, 256>>>(
        pred[0], pred[1], pred[2],
        before[0], before[1], before[2],
        lap[0], lap[1], lap[2], gt);

    // epilogue with Programmatic Dependent Launch: overlaps its independent
    // prologue with the chamfer kernel's draining tail.
    {
        cudaLaunchConfig_t cfg = {};
        cfg.gridDim = dim3(EPI_BLOCKS, 1, 1);
        cfg.blockDim = dim3(256, 1, 1);
        cfg.dynamicSmemBytes = 0;
        cfg.stream = 0;
        cudaLaunchAttribute attr[1];
        attr[0].id = cudaLaunchAttributeProgrammaticStreamSerialization;
        attr[0].val.programmaticStreamSerializationAllowed = 1;
        cfg.attrs = attr;
        cfg.numAttrs = 1;
        float* outp = (float*)d_out;
        cudaLaunchKernelEx(&cfg, epi_kernel,
                           pred[0], pred[1], pred[2],
                           edges[0], edges[1], edges[2],
                           gt, gtn, outp);
    }
}